// round 1
// baseline (speedup 1.0000x reference)
#include <cuda_runtime.h>
#include <stdint.h>

// Problem constants (fixed shapes for this problem instance)
#define NB    16
#define HWPIX (512 * 512)          // pixels per image
#define NPIX  (NB * HWPIX)         // total pixels
#define WPI   8192                 // 32-bit words per bitpacked image (512 rows * 16 words)
#define SMOOTHV 1e-6

// Scratch (no allocations allowed): bitpacked binarized images / skeletons
__device__ uint32_t g_pbits[NB * WPI];
__device__ uint32_t g_tbits[NB * WPI];
// accumulators: [0]=inter_c0 [1]=inter_c1 [2]=sum_p0 [3]=sum_p1 [4]=focal_sum [5]=cnt_true1
__device__ double g_acc[6];

__global__ void k_init() {
    if (threadIdx.x < 6) g_acc[threadIdx.x] = 0.0;
}

// ---------------------------------------------------------------------------
// Kernel 1: softmax + focal + dice partials + bitpacked binarization
// grid: 512 blocks x 1024 threads, 8 pixels / thread (warp handles 256 px,
// each k-step is one 32-pixel word -> __ballot_sync produces the word).
// ---------------------------------------------------------------------------
__global__ __launch_bounds__(1024) void k_pixel(const float* __restrict__ logits,
                                                const int* __restrict__ truth) {
    const int tid  = threadIdx.x;
    const int lane = tid & 31;
    const int warp = tid >> 5;
    const int base = blockIdx.x * 8192 + warp * 256;

    float aI0 = 0.f, aI1 = 0.f, aS0 = 0.f, aS1 = 0.f, aF = 0.f, aC1 = 0.f;

#pragma unroll
    for (int k = 0; k < 8; ++k) {
        int pix = base + k * 32 + lane;
        int b   = pix >> 18;            // / HWPIX
        int i   = pix & (HWPIX - 1);
        float l0 = logits[(size_t)b * 2 * HWPIX + i];
        float l1 = logits[(size_t)b * 2 * HWPIX + HWPIX + i];
        int   tv = truth[pix];

        float d  = l0 - l1;             // logp1 = -log(1+e^d)
        float ad = fabsf(d);
        float u  = __expf(-ad);         // e^{-|d|} in (0,1]
        float pmax = 1.0f / (1.0f + u); // prob of argmax class
        float pmin = 1.0f - pmax;
        bool  pb = (d < 0.0f);          // pred class-1 (p1 > 0.5 <=> l1 > l0)
        bool  tb = (tv > 0);
        float p1 = pb ? pmax : pmin;
        float p0 = 1.0f - p1;
        float lg = __logf(1.0f + u);    // log1p(u)
        float ce = (pb == tb) ? lg : (ad + lg);   // -log p_true (stable)
        float pt = tb ? p1 : p0;
        float om = 1.0f - pt;
        aF += 0.25f * om * om * ce;     // ALPHA*(1-pt)^GAMMA*ce
        if (tb) { aI1 += p1; aC1 += 1.0f; } else { aI0 += p0; }
        aS0 += p0; aS1 += p1;

        unsigned pm = __ballot_sync(0xffffffffu, pb);
        unsigned tm = __ballot_sync(0xffffffffu, tb);
        if (lane == 0) {
            int w = (base + k * 32) >> 5;   // global word index (image-major layout)
            g_pbits[w] = pm;
            g_tbits[w] = tm;
        }
    }

    // block reduction -> 6 double atomics per block (512 blocks total)
    __shared__ float red[32][6];
#pragma unroll
    for (int off = 16; off; off >>= 1) {
        aI0 += __shfl_down_sync(0xffffffffu, aI0, off);
        aI1 += __shfl_down_sync(0xffffffffu, aI1, off);
        aS0 += __shfl_down_sync(0xffffffffu, aS0, off);
        aS1 += __shfl_down_sync(0xffffffffu, aS1, off);
        aF  += __shfl_down_sync(0xffffffffu, aF , off);
        aC1 += __shfl_down_sync(0xffffffffu, aC1, off);
    }
    if (lane == 0) {
        red[warp][0] = aI0; red[warp][1] = aI1; red[warp][2] = aS0;
        red[warp][3] = aS1; red[warp][4] = aF;  red[warp][5] = aC1;
    }
    __syncthreads();
    if (warp == 0) {
        float v0 = red[lane][0], v1 = red[lane][1], v2 = red[lane][2];
        float v3 = red[lane][3], v4 = red[lane][4], v5 = red[lane][5];
#pragma unroll
        for (int off = 16; off; off >>= 1) {
            v0 += __shfl_down_sync(0xffffffffu, v0, off);
            v1 += __shfl_down_sync(0xffffffffu, v1, off);
            v2 += __shfl_down_sync(0xffffffffu, v2, off);
            v3 += __shfl_down_sync(0xffffffffu, v3, off);
            v4 += __shfl_down_sync(0xffffffffu, v4, off);
            v5 += __shfl_down_sync(0xffffffffu, v5, off);
        }
        if (lane == 0) {
            atomicAdd(&g_acc[0], (double)v0);
            atomicAdd(&g_acc[1], (double)v1);
            atomicAdd(&g_acc[2], (double)v2);
            atomicAdd(&g_acc[3], (double)v3);
            atomicAdd(&g_acc[4], (double)v4);
            atomicAdd(&g_acc[5], (double)v5);
        }
    }
}

// ---------------------------------------------------------------------------
// Kernel 2: Zhang-Suen skeletonization, one CTA per image, bit-parallel.
// Image bitpacked in 32KB shared memory; iterate to convergence in-kernel.
// ---------------------------------------------------------------------------
__device__ __forceinline__ void fadd(uint32_t a, uint32_t b, uint32_t c,
                                     uint32_t& s, uint32_t& cy) {
    uint32_t x = a ^ b; s = x ^ c; cy = (a & b) | (x & c);
}
__device__ __forceinline__ void hadd(uint32_t a, uint32_t b,
                                     uint32_t& s, uint32_t& cy) {
    s = a ^ b; cy = a & b;
}

template <int SUB>
__device__ __forceinline__ uint32_t thin_word(const uint32_t* img, int w) {
    uint32_t cur = img[w];
    if (!cur) return 0u;                 // nothing to remove in an empty word
    int row = w >> 4, col = w & 15;
    bool rU = row > 0, rD = row < 511, cL = col > 0, cR = col < 15;
    uint32_t up = rU ? img[w - 16] : 0u;
    uint32_t dn = rD ? img[w + 16] : 0u;
    uint32_t lf = cL ? img[w - 1]  : 0u;
    uint32_t rt = cR ? img[w + 1]  : 0u;
    uint32_t ul = (rU && cL) ? img[w - 17] : 0u;
    uint32_t ur = (rU && cR) ? img[w - 15] : 0u;
    uint32_t dl = (rD && cL) ? img[w + 15] : 0u;
    uint32_t dr = (rD && cR) ? img[w + 17] : 0u;

    // bit j of a word = pixel at column 32*col + j; West = bit j-1
    uint32_t p2 = up;                                 // N
    uint32_t p3 = (up >> 1) | (ur << 31);             // NE
    uint32_t p4 = (cur >> 1) | (rt << 31);            // E
    uint32_t p5 = (dn >> 1) | (dr << 31);             // SE
    uint32_t p6 = dn;                                 // S
    uint32_t p7 = (dn << 1) | (dl >> 31);             // SW
    uint32_t p8 = (cur << 1) | (lf >> 31);            // W
    uint32_t p9 = (up << 1) | (ul >> 31);             // NW

    // B = per-bit neighbor count via carry-save adders -> bits S0..S3
    uint32_t s1, c1, s2, c2, s3, c3, S0, c4, s5, c5, S1, c6, S2, S3;
    fadd(p2, p3, p4, s1, c1);
    fadd(p5, p6, p7, s2, c2);
    hadd(p8, p9, s3, c3);
    fadd(s1, s2, s3, S0, c4);
    fadd(c1, c2, c3, s5, c5);
    hadd(s5, c4, S1, c6);
    hadd(c5, c6, S2, S3);
    uint32_t ge2 = S1 | S2 | S3;
    uint32_t le6 = ~(S3 | (S2 & S1 & S0));

    // A = per-bit count of 0->1 transitions in circular p2..p9
    uint32_t t0 = ~p2 & p3, t1 = ~p3 & p4, t2 = ~p4 & p5, t3 = ~p5 & p6;
    uint32_t t4 = ~p6 & p7, t5 = ~p7 & p8, t6 = ~p8 & p9, t7 = ~p9 & p2;
    uint32_t a1, d1, a2, d2, a3, d3, A0, d4, a5, d5, A1, d6, A2, A3;
    fadd(t0, t1, t2, a1, d1);
    fadd(t3, t4, t5, a2, d2);
    hadd(t6, t7, a3, d3);
    fadd(a1, a2, a3, A0, d4);
    fadd(d1, d2, d3, a5, d5);
    hadd(a5, d4, A1, d6);
    hadd(d5, d6, A2, A3);
    uint32_t aeq1 = A0 & ~(A1 | A2 | A3);

    uint32_t cond34;
    if (SUB == 0)
        cond34 = ~(p4 & p6 & (p2 | p8));   // ~(p2p4p6) & ~(p4p6p8)
    else
        cond34 = ~(p2 & p8 & (p4 | p6));   // ~(p2p4p8) & ~(p2p6p8)

    uint32_t remove = cur & ge2 & le6 & aeq1 & cond34;
    return cur & ~remove;
}

__global__ __launch_bounds__(1024) void k_skel() {
    __shared__ uint32_t img[WPI];       // 32 KB
    __shared__ int s_flag;
    const int tid = threadIdx.x;
    uint32_t* src = (blockIdx.x < NB)
                        ? &g_pbits[blockIdx.x * WPI]
                        : &g_tbits[(blockIdx.x - NB) * WPI];
#pragma unroll
    for (int k = 0; k < 8; ++k) img[tid + k * 1024] = src[tid + k * 1024];
    __syncthreads();

    for (int iter = 0; iter < 4096; ++iter) {
        int changed = 0;
        uint32_t nw[8];
        // sub-iteration 0
#pragma unroll
        for (int k = 0; k < 8; ++k) {
            int w = tid + k * 1024;
            uint32_t o = img[w];
            uint32_t n = thin_word<0>(img, w);
            nw[k] = n;
            changed |= (n != o);
        }
        __syncthreads();
#pragma unroll
        for (int k = 0; k < 8; ++k) img[tid + k * 1024] = nw[k];
        __syncthreads();
        // sub-iteration 1
#pragma unroll
        for (int k = 0; k < 8; ++k) {
            int w = tid + k * 1024;
            uint32_t o = img[w];
            uint32_t n = thin_word<1>(img, w);
            nw[k] = n;
            changed |= (n != o);
        }
        if (tid == 0) s_flag = 0;
        __syncthreads();                 // reset visible; reads done before writes
#pragma unroll
        for (int k = 0; k < 8; ++k) img[tid + k * 1024] = nw[k];
        if (changed) s_flag = 1;
        __syncthreads();                 // writes + flag visible
        if (!s_flag) break;              // uniform across block
    }

#pragma unroll
    for (int k = 0; k < 8; ++k) src[tid + k * 1024] = img[tid + k * 1024];
}

// ---------------------------------------------------------------------------
// Kernel 3: per-batch clDice popcounts + final scalar combine
// ---------------------------------------------------------------------------
__global__ __launch_bounds__(1024) void k_final(float* __restrict__ out) {
    const int tid = threadIdx.x, lane = tid & 31, warp = tid >> 5;
    __shared__ int sI[32], sP[32], sT[32];
    __shared__ double scl;
    if (tid == 0) scl = 0.0;
    __syncthreads();

    for (int b = 0; b < NB; ++b) {
        int li = 0, lp = 0, lt = 0;
#pragma unroll
        for (int k = 0; k < 8; ++k) {
            int w = b * WPI + tid + k * 1024;
            uint32_t p = g_pbits[w], t = g_tbits[w];
            li += __popc(p & t);
            lp += __popc(p);
            lt += __popc(t);
        }
#pragma unroll
        for (int off = 16; off; off >>= 1) {
            li += __shfl_down_sync(0xffffffffu, li, off);
            lp += __shfl_down_sync(0xffffffffu, lp, off);
            lt += __shfl_down_sync(0xffffffffu, lt, off);
        }
        if (lane == 0) { sI[warp] = li; sP[warp] = lp; sT[warp] = lt; }
        __syncthreads();
        if (tid == 0) {
            int I = 0, P = 0, T = 0;
            for (int j = 0; j < 32; ++j) { I += sI[j]; P += sP[j]; T += sT[j]; }
            scl += (2.0 * (double)I + SMOOTHV) / ((double)(P + T) + SMOOTHV);
        }
        __syncthreads();
    }

    if (tid == 0) {
        double I0 = g_acc[0], I1 = g_acc[1], S0v = g_acc[2];
        double S1v = g_acc[3], F = g_acc[4], C1 = g_acc[5];
        double C0 = (double)NPIX - C1;
        double dice = 1.0 - 0.5 * ((2.0 * I0 + SMOOTHV) / (S0v + C0 + SMOOTHV) +
                                   (2.0 * I1 + SMOOTHV) / (S1v + C1 + SMOOTHV));
        double focal = F / (double)NPIX;
        double cl = 1.0 - scl / (double)NB;
        out[0] = (float)(0.7 * cl + 0.1 * dice + 0.2 * focal);
    }
}

extern "C" void kernel_launch(void* const* d_in, const int* in_sizes, int n_in,
                              void* d_out, int out_size) {
    const float* logits = (const float*)d_in[0];   // [16,2,512,512] f32
    const int*   truth  = (const int*)d_in[1];     // [16,512,512] i32
    float* out = (float*)d_out;

    k_init<<<1, 32>>>();
    k_pixel<<<512, 1024>>>(logits, truth);
    k_skel<<<32, 1024>>>();
    k_final<<<1, 1024>>>(out);
}

// round 2
// speedup vs baseline: 1.8847x; 1.8847x over previous
#include <cuda_runtime.h>
#include <cooperative_groups.h>
#include <stdint.h>

namespace cg = cooperative_groups;

// Problem constants (fixed shapes for this problem instance)
#define NB    16
#define HWPIX (512 * 512)          // pixels per image
#define NPIX  (NB * HWPIX)         // total pixels
#define WPI   8192                 // 32-bit words per bitpacked image (512 rows * 16 words)
#define SMOOTHV 1e-6
#define CSIZE 4                    // CTAs per image (cluster size)
#define WPC   (WPI / CSIZE)        // 2048 words per CTA
#define ROWS_PER_CTA 128

// Scratch (no allocations allowed): bitpacked binarized images / skeletons
__device__ uint32_t g_pbits[NB * WPI];
__device__ uint32_t g_tbits[NB * WPI];
// accumulators: [0]=inter_c0 [1]=inter_c1 [2]=sum_p0 [3]=sum_p1 [4]=focal_sum
//               [5]=cnt_true1 [6]=cldice_ratio_sum
__device__ double g_acc[7];

__global__ void k_init() {
    if (threadIdx.x < 7) g_acc[threadIdx.x] = 0.0;
}

// ---------------------------------------------------------------------------
// Kernel 1: softmax + focal + dice partials + bitpacked binarization
// ---------------------------------------------------------------------------
__global__ __launch_bounds__(1024) void k_pixel(const float* __restrict__ logits,
                                                const int* __restrict__ truth) {
    const int tid  = threadIdx.x;
    const int lane = tid & 31;
    const int warp = tid >> 5;
    const int base = blockIdx.x * 8192 + warp * 256;

    float aI0 = 0.f, aI1 = 0.f, aS0 = 0.f, aS1 = 0.f, aF = 0.f, aC1 = 0.f;

#pragma unroll
    for (int k = 0; k < 8; ++k) {
        int pix = base + k * 32 + lane;
        int b   = pix >> 18;            // / HWPIX
        int i   = pix & (HWPIX - 1);
        float l0 = logits[(size_t)b * 2 * HWPIX + i];
        float l1 = logits[(size_t)b * 2 * HWPIX + HWPIX + i];
        int   tv = truth[pix];

        float d  = l0 - l1;             // logp1 = -log(1+e^d)
        float ad = fabsf(d);
        float u  = __expf(-ad);         // e^{-|d|} in (0,1]
        float pmax = 1.0f / (1.0f + u); // prob of argmax class
        float pmin = 1.0f - pmax;
        bool  pb = (d < 0.0f);          // pred class-1 (p1 > 0.5 <=> l1 > l0)
        bool  tb = (tv > 0);
        float p1 = pb ? pmax : pmin;
        float p0 = 1.0f - p1;
        float lg = __logf(1.0f + u);    // log1p(u)
        float ce = (pb == tb) ? lg : (ad + lg);   // -log p_true (stable)
        float pt = tb ? p1 : p0;
        float om = 1.0f - pt;
        aF += 0.25f * om * om * ce;     // ALPHA*(1-pt)^GAMMA*ce
        if (tb) { aI1 += p1; aC1 += 1.0f; } else { aI0 += p0; }
        aS0 += p0; aS1 += p1;

        unsigned pm = __ballot_sync(0xffffffffu, pb);
        unsigned tm = __ballot_sync(0xffffffffu, tb);
        if (lane == 0) {
            int w = (base + k * 32) >> 5;   // global word index (image-major)
            g_pbits[w] = pm;
            g_tbits[w] = tm;
        }
    }

    __shared__ float red[32][6];
#pragma unroll
    for (int off = 16; off; off >>= 1) {
        aI0 += __shfl_down_sync(0xffffffffu, aI0, off);
        aI1 += __shfl_down_sync(0xffffffffu, aI1, off);
        aS0 += __shfl_down_sync(0xffffffffu, aS0, off);
        aS1 += __shfl_down_sync(0xffffffffu, aS1, off);
        aF  += __shfl_down_sync(0xffffffffu, aF , off);
        aC1 += __shfl_down_sync(0xffffffffu, aC1, off);
    }
    if (lane == 0) {
        red[warp][0] = aI0; red[warp][1] = aI1; red[warp][2] = aS0;
        red[warp][3] = aS1; red[warp][4] = aF;  red[warp][5] = aC1;
    }
    __syncthreads();
    if (warp == 0) {
        float v0 = red[lane][0], v1 = red[lane][1], v2 = red[lane][2];
        float v3 = red[lane][3], v4 = red[lane][4], v5 = red[lane][5];
#pragma unroll
        for (int off = 16; off; off >>= 1) {
            v0 += __shfl_down_sync(0xffffffffu, v0, off);
            v1 += __shfl_down_sync(0xffffffffu, v1, off);
            v2 += __shfl_down_sync(0xffffffffu, v2, off);
            v3 += __shfl_down_sync(0xffffffffu, v3, off);
            v4 += __shfl_down_sync(0xffffffffu, v4, off);
            v5 += __shfl_down_sync(0xffffffffu, v5, off);
        }
        if (lane == 0) {
            atomicAdd(&g_acc[0], (double)v0);
            atomicAdd(&g_acc[1], (double)v1);
            atomicAdd(&g_acc[2], (double)v2);
            atomicAdd(&g_acc[3], (double)v3);
            atomicAdd(&g_acc[4], (double)v4);
            atomicAdd(&g_acc[5], (double)v5);
        }
    }
}

// ---------------------------------------------------------------------------
// Kernel 2: Zhang-Suen skeletonization, 4-CTA cluster per image, bit-parallel.
// Each CTA owns 128 rows in shared memory with 2 halo rows refreshed via DSMEM.
// ---------------------------------------------------------------------------
__device__ __forceinline__ void fadd(uint32_t a, uint32_t b, uint32_t c,
                                     uint32_t& s, uint32_t& cy) {
    uint32_t x = a ^ b; s = x ^ c; cy = (a & b) | (x & c);
}
__device__ __forceinline__ void hadd(uint32_t a, uint32_t b,
                                     uint32_t& s, uint32_t& cy) {
    s = a ^ b; cy = a & b;
}

template <int SUB>
__device__ __forceinline__ uint32_t thin_word(const uint32_t* img, int idx, int c) {
    uint32_t cur = img[idx];
    if (!cur) return 0u;
    bool cL = c > 0, cR = c < 15;
    uint32_t up = img[idx - 16];
    uint32_t dn = img[idx + 16];
    uint32_t lf = cL ? img[idx - 1]  : 0u;
    uint32_t rt = cR ? img[idx + 1]  : 0u;
    uint32_t ul = cL ? img[idx - 17] : 0u;
    uint32_t ur = cR ? img[idx - 15] : 0u;
    uint32_t dl = cL ? img[idx + 15] : 0u;
    uint32_t dr = cR ? img[idx + 17] : 0u;

    uint32_t p2 = up;                                 // N
    uint32_t p3 = (up >> 1) | (ur << 31);             // NE
    uint32_t p4 = (cur >> 1) | (rt << 31);            // E
    uint32_t p5 = (dn >> 1) | (dr << 31);             // SE
    uint32_t p6 = dn;                                 // S
    uint32_t p7 = (dn << 1) | (dl >> 31);             // SW
    uint32_t p8 = (cur << 1) | (lf >> 31);            // W
    uint32_t p9 = (up << 1) | (ul >> 31);             // NW

    // B = per-bit neighbor count via carry-save adders
    uint32_t s1, c1, s2, c2, s3, c3, S0, c4, s5, c5, S1, c6, S2, S3;
    fadd(p2, p3, p4, s1, c1);
    fadd(p5, p6, p7, s2, c2);
    hadd(p8, p9, s3, c3);
    fadd(s1, s2, s3, S0, c4);
    fadd(c1, c2, c3, s5, c5);
    hadd(s5, c4, S1, c6);
    hadd(c5, c6, S2, S3);
    uint32_t ge2 = S1 | S2 | S3;
    uint32_t le6 = ~(S3 | (S2 & S1 & S0));

    // A = per-bit count of 0->1 transitions in circular p2..p9
    uint32_t t0 = ~p2 & p3, t1 = ~p3 & p4, t2 = ~p4 & p5, t3 = ~p5 & p6;
    uint32_t t4 = ~p6 & p7, t5 = ~p7 & p8, t6 = ~p8 & p9, t7 = ~p9 & p2;
    uint32_t a1, d1, a2, d2, a3, d3, A0, d4, a5, d5, A1, d6, A2, A3;
    fadd(t0, t1, t2, a1, d1);
    fadd(t3, t4, t5, a2, d2);
    hadd(t6, t7, a3, d3);
    fadd(a1, a2, a3, A0, d4);
    fadd(d1, d2, d3, a5, d5);
    hadd(a5, d4, A1, d6);
    hadd(d5, d6, A2, A3);
    uint32_t aeq1 = A0 & ~(A1 | A2 | A3);

    uint32_t cond34;
    if (SUB == 0)
        cond34 = ~(p4 & p6 & (p2 | p8));   // ~(p2p4p6) & ~(p4p6p8)
    else
        cond34 = ~(p2 & p8 & (p4 | p6));   // ~(p2p4p8) & ~(p2p6p8)

    uint32_t remove = cur & ge2 & le6 & aeq1 & cond34;
    return cur & ~remove;
}

__global__ __launch_bounds__(1024) __cluster_dims__(CSIZE, 1, 1)
void k_skel() {
    // rows 0..129: row 0 = up halo, rows 1..128 local, row 129 = down halo
    __shared__ uint32_t img[(ROWS_PER_CTA + 2) * 16];
    __shared__ int s_flag;
    __shared__ int s_rem[CSIZE];
    const int tid = threadIdx.x;
    cg::cluster_group cluster = cg::this_cluster();
    const unsigned rank = cluster.block_rank();
    const unsigned image = blockIdx.x / CSIZE;

    uint32_t* src = (image < NB) ? &g_pbits[image * WPI]
                                 : &g_tbits[(image - NB) * WPI];
    uint32_t* my = src + rank * WPC;

    uint32_t* upimg = (rank > 0)
        ? (uint32_t*)cluster.map_shared_rank((void*)img, rank - 1) : nullptr;
    uint32_t* dnimg = (rank + 1 < CSIZE)
        ? (uint32_t*)cluster.map_shared_rank((void*)img, rank + 1) : nullptr;

    // load own 128 rows into smem rows 1..128
#pragma unroll
    for (int k = 0; k < 2; ++k) {
        int w = tid + k * 1024;
        img[16 + w] = my[w];
    }
    if (tid == 0) s_flag = 0;
    cluster.sync();     // all loads done before anyone reads peer halos

    for (int iter = 0; iter < 4096; ++iter) {
        int changed = 0;
        uint32_t nw[2];

#pragma unroll
        for (int sub = 0; sub < 2; ++sub) {
            // refresh halo rows from peers (DSMEM)
            if (tid < 16)
                img[tid] = upimg ? upimg[ROWS_PER_CTA * 16 + tid] : 0u;
            else if (tid < 32)
                img[(ROWS_PER_CTA + 1) * 16 + (tid - 16)] =
                    dnimg ? dnimg[16 + (tid - 16)] : 0u;
            __syncthreads();

#pragma unroll
            for (int k = 0; k < 2; ++k) {
                int w = tid + k * 1024;
                uint32_t n = (sub == 0) ? thin_word<0>(img, 16 + w, w & 15)
                                        : thin_word<1>(img, 16 + w, w & 15);
                nw[k] = n;
                changed |= (n != img[16 + w]);
            }
            cluster.sync();     // all reads (incl. peers' halo reads) complete
#pragma unroll
            for (int k = 0; k < 2; ++k) img[16 + tid + k * 1024] = nw[k];
            if (sub == 1 && changed) s_flag = 1;
            cluster.sync();     // writes (and flag) visible cluster-wide
        }

        // cluster-wide convergence decision (uniform across all CTAs)
        if (tid < CSIZE)
            s_rem[tid] = *(volatile int*)cluster.map_shared_rank((void*)&s_flag, tid);
        __syncthreads();
        int any = s_rem[0] | s_rem[1] | s_rem[2] | s_rem[3];
        if (!any) break;
        cluster.sync();         // all peers read flags before reset
        if (tid == 0) s_flag = 0;
    }

#pragma unroll
    for (int k = 0; k < 2; ++k) {
        int w = tid + k * 1024;
        my[w] = img[16 + w];
    }
}

// ---------------------------------------------------------------------------
// Kernel 3: per-batch clDice popcounts (16 blocks), ratio -> atomic double
// ---------------------------------------------------------------------------
__global__ __launch_bounds__(1024) void k_cldice() {
    const int tid = threadIdx.x, lane = tid & 31, warp = tid >> 5;
    const int b = blockIdx.x;
    __shared__ int sI[32], sP[32], sT[32];

    int li = 0, lp = 0, lt = 0;
#pragma unroll
    for (int k = 0; k < 8; ++k) {
        int w = b * WPI + tid + k * 1024;
        uint32_t p = g_pbits[w], t = g_tbits[w];
        li += __popc(p & t);
        lp += __popc(p);
        lt += __popc(t);
    }
#pragma unroll
    for (int off = 16; off; off >>= 1) {
        li += __shfl_down_sync(0xffffffffu, li, off);
        lp += __shfl_down_sync(0xffffffffu, lp, off);
        lt += __shfl_down_sync(0xffffffffu, lt, off);
    }
    if (lane == 0) { sI[warp] = li; sP[warp] = lp; sT[warp] = lt; }
    __syncthreads();
    if (warp == 0) {
        int vI = sI[lane], vP = sP[lane], vT = sT[lane];
#pragma unroll
        for (int off = 16; off; off >>= 1) {
            vI += __shfl_down_sync(0xffffffffu, vI, off);
            vP += __shfl_down_sync(0xffffffffu, vP, off);
            vT += __shfl_down_sync(0xffffffffu, vT, off);
        }
        if (lane == 0) {
            double ratio = (2.0 * (double)vI + SMOOTHV) /
                           ((double)(vP + vT) + SMOOTHV);
            atomicAdd(&g_acc[6], ratio);
        }
    }
}

// ---------------------------------------------------------------------------
// Kernel 4: final scalar combine
// ---------------------------------------------------------------------------
__global__ void k_combine(float* __restrict__ out) {
    double I0 = g_acc[0], I1 = g_acc[1], S0v = g_acc[2];
    double S1v = g_acc[3], F = g_acc[4], C1 = g_acc[5];
    double C0 = (double)NPIX - C1;
    double dice = 1.0 - 0.5 * ((2.0 * I0 + SMOOTHV) / (S0v + C0 + SMOOTHV) +
                               (2.0 * I1 + SMOOTHV) / (S1v + C1 + SMOOTHV));
    double focal = F / (double)NPIX;
    double cl = 1.0 - g_acc[6] / (double)NB;
    out[0] = (float)(0.7 * cl + 0.1 * dice + 0.2 * focal);
}

extern "C" void kernel_launch(void* const* d_in, const int* in_sizes, int n_in,
                              void* d_out, int out_size) {
    const float* logits = (const float*)d_in[0];   // [16,2,512,512] f32
    const int*   truth  = (const int*)d_in[1];     // [16,512,512] i32
    float* out = (float*)d_out;

    k_init<<<1, 32>>>();
    k_pixel<<<512, 1024>>>(logits, truth);
    k_skel<<<NB * 2 * CSIZE, 1024>>>();
    k_cldice<<<NB, 1024>>>();
    k_combine<<<1, 1>>>(out);
}

// round 6
// speedup vs baseline: 1.9438x; 1.0313x over previous
#include <cuda_runtime.h>
#include <cooperative_groups.h>
#include <stdint.h>

namespace cg = cooperative_groups;

// Problem constants (fixed shapes for this problem instance)
#define NB    16
#define HWPIX (512 * 512)          // pixels per image
#define NPIX  (NB * HWPIX)         // total pixels
#define WPI   8192                 // 32-bit words per bitpacked image (512 rows * 16 words)
#define SMOOTHV 1e-6
#define CSIZE 4                    // CTAs per image (cluster size)
#define WPC   (WPI / CSIZE)        // 2048 words per CTA
#define RPC   128                  // rows per CTA

// Scratch: bitpacked binarized images / skeletons
__device__ uint32_t g_pbits[NB * WPI];
__device__ uint32_t g_tbits[NB * WPI];
// float accumulators: [0]=inter_c0 [1]=inter_c1 [2]=sum_p0 [3]=sum_p1 [4]=focal [5]=cnt_true1
__device__ double g_acc[6];
// clDice int counts: per image {inter, sum_p, sum_t}
__device__ int g_cnt[NB * 3];

__global__ void k_init() {
    if (threadIdx.x < 6) g_acc[threadIdx.x] = 0.0;
    if (threadIdx.x < NB * 3) g_cnt[threadIdx.x] = 0;
}

// ---------------------------------------------------------------------------
// Kernel 1: softmax + focal + dice partials + bitpacked binarization
// ---------------------------------------------------------------------------
__global__ __launch_bounds__(1024) void k_pixel(const float* __restrict__ logits,
                                                const int* __restrict__ truth) {
    const int tid  = threadIdx.x;
    const int lane = tid & 31;
    const int warp = tid >> 5;
    const int base = blockIdx.x * 8192 + warp * 256;

    float aI0 = 0.f, aI1 = 0.f, aS0 = 0.f, aS1 = 0.f, aF = 0.f, aC1 = 0.f;

#pragma unroll
    for (int k = 0; k < 8; ++k) {
        int pix = base + k * 32 + lane;
        int b   = pix >> 18;            // / HWPIX
        int i   = pix & (HWPIX - 1);
        float l0 = logits[(size_t)b * 2 * HWPIX + i];
        float l1 = logits[(size_t)b * 2 * HWPIX + HWPIX + i];
        int   tv = truth[pix];

        float d  = l0 - l1;
        float ad = fabsf(d);
        float u  = __expf(-ad);
        float pmax = 1.0f / (1.0f + u);
        float pmin = 1.0f - pmax;
        bool  pb = (d < 0.0f);
        bool  tb = (tv > 0);
        float p1 = pb ? pmax : pmin;
        float p0 = 1.0f - p1;
        float lg = __logf(1.0f + u);
        float ce = (pb == tb) ? lg : (ad + lg);
        float pt = tb ? p1 : p0;
        float om = 1.0f - pt;
        aF += 0.25f * om * om * ce;
        if (tb) { aI1 += p1; aC1 += 1.0f; } else { aI0 += p0; }
        aS0 += p0; aS1 += p1;

        unsigned pm = __ballot_sync(0xffffffffu, pb);
        unsigned tm = __ballot_sync(0xffffffffu, tb);
        if (lane == 0) {
            int w = (base + k * 32) >> 5;
            g_pbits[w] = pm;
            g_tbits[w] = tm;
        }
    }

    __shared__ float red[32][6];
#pragma unroll
    for (int off = 16; off; off >>= 1) {
        aI0 += __shfl_down_sync(0xffffffffu, aI0, off);
        aI1 += __shfl_down_sync(0xffffffffu, aI1, off);
        aS0 += __shfl_down_sync(0xffffffffu, aS0, off);
        aS1 += __shfl_down_sync(0xffffffffu, aS1, off);
        aF  += __shfl_down_sync(0xffffffffu, aF , off);
        aC1 += __shfl_down_sync(0xffffffffu, aC1, off);
    }
    if (lane == 0) {
        red[warp][0] = aI0; red[warp][1] = aI1; red[warp][2] = aS0;
        red[warp][3] = aS1; red[warp][4] = aF;  red[warp][5] = aC1;
    }
    __syncthreads();
    if (warp == 0) {
        float v0 = red[lane][0], v1 = red[lane][1], v2 = red[lane][2];
        float v3 = red[lane][3], v4 = red[lane][4], v5 = red[lane][5];
#pragma unroll
        for (int off = 16; off; off >>= 1) {
            v0 += __shfl_down_sync(0xffffffffu, v0, off);
            v1 += __shfl_down_sync(0xffffffffu, v1, off);
            v2 += __shfl_down_sync(0xffffffffu, v2, off);
            v3 += __shfl_down_sync(0xffffffffu, v3, off);
            v4 += __shfl_down_sync(0xffffffffu, v4, off);
            v5 += __shfl_down_sync(0xffffffffu, v5, off);
        }
        if (lane == 0) {
            atomicAdd(&g_acc[0], (double)v0);
            atomicAdd(&g_acc[1], (double)v1);
            atomicAdd(&g_acc[2], (double)v2);
            atomicAdd(&g_acc[3], (double)v3);
            atomicAdd(&g_acc[4], (double)v4);
            atomicAdd(&g_acc[5], (double)v5);
        }
    }
}

// ---------------------------------------------------------------------------
// Kernel 2: Zhang-Suen skeletonization, 4-CTA cluster per image, bit-parallel,
// double-buffered (1 cluster.sync per sub-pass) + stable-row skipping.
// ---------------------------------------------------------------------------
__device__ __forceinline__ void fadd(uint32_t a, uint32_t b, uint32_t c,
                                     uint32_t& s, uint32_t& cy) {
    uint32_t x = a ^ b; s = x ^ c; cy = (a & b) | (x & c);
}
__device__ __forceinline__ void hadd(uint32_t a, uint32_t b,
                                     uint32_t& s, uint32_t& cy) {
    s = a ^ b; cy = a & b;
}

template <int SUB>
__device__ __forceinline__ uint32_t thin_word(const uint32_t* img, int idx, int c) {
    uint32_t cur = img[idx];
    if (!cur) return 0u;
    bool cL = c > 0, cR = c < 15;
    uint32_t up = img[idx - 16];
    uint32_t dn = img[idx + 16];
    uint32_t lf = cL ? img[idx - 1]  : 0u;
    uint32_t rt = cR ? img[idx + 1]  : 0u;
    uint32_t ul = cL ? img[idx - 17] : 0u;
    uint32_t ur = cR ? img[idx - 15] : 0u;
    uint32_t dl = cL ? img[idx + 15] : 0u;
    uint32_t dr = cR ? img[idx + 17] : 0u;

    uint32_t p2 = up;                                 // N
    uint32_t p3 = (up >> 1) | (ur << 31);             // NE
    uint32_t p4 = (cur >> 1) | (rt << 31);            // E
    uint32_t p5 = (dn >> 1) | (dr << 31);             // SE
    uint32_t p6 = dn;                                 // S
    uint32_t p7 = (dn << 1) | (dl >> 31);             // SW
    uint32_t p8 = (cur << 1) | (lf >> 31);             // W
    uint32_t p9 = (up << 1) | (ul >> 31);             // NW

    uint32_t s1, c1, s2, c2, s3, c3, S0, c4, s5, c5, S1, c6, S2, S3;
    fadd(p2, p3, p4, s1, c1);
    fadd(p5, p6, p7, s2, c2);
    hadd(p8, p9, s3, c3);
    fadd(s1, s2, s3, S0, c4);
    fadd(c1, c2, c3, s5, c5);
    hadd(s5, c4, S1, c6);
    hadd(c5, c6, S2, S3);
    uint32_t ge2 = S1 | S2 | S3;
    uint32_t le6 = ~(S3 | (S2 & S1 & S0));

    uint32_t t0 = ~p2 & p3, t1 = ~p3 & p4, t2 = ~p4 & p5, t3 = ~p5 & p6;
    uint32_t t4 = ~p6 & p7, t5 = ~p7 & p8, t6 = ~p8 & p9, t7 = ~p9 & p2;
    uint32_t a1, d1, a2, d2, a3, d3, A0, d4, a5, d5, A1, d6, A2, A3;
    fadd(t0, t1, t2, a1, d1);
    fadd(t3, t4, t5, a2, d2);
    hadd(t6, t7, a3, d3);
    fadd(a1, a2, a3, A0, d4);
    fadd(d1, d2, d3, a5, d5);
    hadd(a5, d4, A1, d6);
    hadd(d5, d6, A2, A3);
    uint32_t aeq1 = A0 & ~(A1 | A2 | A3);

    uint32_t cond34;
    if (SUB == 0)
        cond34 = ~(p4 & p6 & (p2 | p8));
    else
        cond34 = ~(p2 & p8 & (p4 | p6));

    uint32_t remove = cur & ge2 & le6 & aeq1 & cond34;
    return cur & ~remove;
}

#define BWORDS ((RPC + 2) * 16)   // 2080 words per buffer (halo rows 0 and 129)

__global__ __launch_bounds__(1024) __cluster_dims__(CSIZE, 1, 1)
void k_skel() {
    __shared__ uint32_t buf[2][BWORDS];   // ping-pong image buffers
    __shared__ int chg[3][RPC + 2];       // per-row change flags, 3 rotating sub-passes
    __shared__ int rc[RPC + 2];           // combined (last two sub-passes) change flags
    __shared__ int s_flag;                // convergence flag for this iteration
    __shared__ int s_rem[CSIZE];

    const int tid = threadIdx.x;
    cg::cluster_group cluster = cg::this_cluster();
    const unsigned rank = cluster.block_rank();
    const unsigned image = blockIdx.x / CSIZE;

    uint32_t* src = (image < NB) ? &g_pbits[image * WPI]
                                 : &g_tbits[(image - NB) * WPI];
    uint32_t* my = src + rank * WPC;

    const bool hasUp = (rank > 0), hasDn = (rank + 1 < CSIZE);
    uint32_t* pu_buf = hasUp ? (uint32_t*)cluster.map_shared_rank((void*)buf, rank - 1) : nullptr;
    uint32_t* pd_buf = hasDn ? (uint32_t*)cluster.map_shared_rank((void*)buf, rank + 1) : nullptr;
    volatile int* pu_chg = hasUp ? (volatile int*)cluster.map_shared_rank((void*)chg, rank - 1) : nullptr;
    volatile int* pd_chg = hasDn ? (volatile int*)cluster.map_shared_rank((void*)chg, rank + 1) : nullptr;

    // load own 128 rows into buf[0] rows 1..128
#pragma unroll
    for (int k = 0; k < 2; ++k) {
        int w = tid + k * 1024;
        buf[0][16 + w] = my[w];
    }
    if (tid < RPC + 2) { chg[1][tid] = 1; chg[2][tid] = 1; }
    if (tid == 0) s_flag = 0;
    cluster.sync();

    int p = 0;                   // current buffer parity
    int tw = 0, t1 = 1, t2 = 2;  // chg slots: write / last pass / pass before

    for (int iter = 0; iter < 512; ++iter) {
        int changed = 0;

#pragma unroll
        for (int sub = 0; sub < 2; ++sub) {
            uint32_t* cur = buf[p];
            uint32_t* nxt = buf[p ^ 1];

            // halo copy + combined-change array + reset write slot
            if (tid < 16) {
                cur[tid] = hasUp ? pu_buf[p * BWORDS + RPC * 16 + tid] : 0u;
            } else if (tid < 32) {
                cur[(RPC + 1) * 16 + (tid - 16)] =
                    hasDn ? pd_buf[p * BWORDS + 16 + (tid - 16)] : 0u;
            } else if (tid < 32 + RPC + 2) {
                int r = tid - 32;
                int v;
                if (r == 0)
                    v = hasUp ? (pu_chg[t1 * (RPC + 2) + RPC] |
                                 pu_chg[t2 * (RPC + 2) + RPC]) : 0;
                else if (r == RPC + 1)
                    v = hasDn ? (pd_chg[t1 * (RPC + 2) + 1] |
                                 pd_chg[t2 * (RPC + 2) + 1]) : 0;
                else
                    v = chg[t1][r] | chg[t2][r];
                rc[r] = v;
                chg[tw][r] = 0;
            }
            __syncthreads();

#pragma unroll
            for (int k = 0; k < 2; ++k) {
                int w = tid + k * 1024;
                int r = (w >> 4) + 1;
                int c = w & 15;
                int idx = 16 + w;
                uint32_t o = cur[idx];
                int act = rc[r - 1] | rc[r] | rc[r + 1];
                uint32_t n = o;
                if (act)
                    n = (sub == 0) ? thin_word<0>(cur, idx, c)
                                   : thin_word<1>(cur, idx, c);
                nxt[idx] = n;
                if (n != o) { chg[tw][r] = 1; changed = 1; }
            }
            if (sub == 1 && changed) s_flag = 1;
            cluster.sync();

            p ^= 1;
            int tmp = t2; t2 = t1; t1 = tw; tw = tmp;
        }

        // cluster-wide convergence decision (R2-style protocol: sync between
        // the peer-flag reads and the flag reset)
        if (tid < CSIZE)
            s_rem[tid] = *(volatile int*)cluster.map_shared_rank((void*)&s_flag, tid);
        __syncthreads();
        int any = s_rem[0] | s_rem[1] | s_rem[2] | s_rem[3];
        if (!any) break;
        cluster.sync();              // all peers finished reading flags
        if (tid == 0) s_flag = 0;    // safe to reset for next iteration
        // next write to s_flag happens after the sub==1 cluster.sync of the
        // next iteration, so this reset is ordered by that sync chain.
    }

    // store result + per-CTA popcounts for clDice (sum_p / sum_t)
    int pcnt = 0;
#pragma unroll
    for (int k = 0; k < 2; ++k) {
        int w = tid + k * 1024;
        uint32_t v = buf[p][16 + w];
        my[w] = v;
        pcnt += __popc(v);
    }
#pragma unroll
    for (int off = 16; off; off >>= 1)
        pcnt += __shfl_down_sync(0xffffffffu, pcnt, off);
    __shared__ int sred[32];
    if ((tid & 31) == 0) sred[tid >> 5] = pcnt;
    __syncthreads();
    if (tid < 32) {
        int v = sred[tid];
#pragma unroll
        for (int off = 16; off; off >>= 1)
            v += __shfl_down_sync(0xffffffffu, v, off);
        if (tid == 0) {
            int img16 = (image < NB) ? (int)image : (int)(image - NB);
            int slot = (image < NB) ? 1 : 2;  // sum_p or sum_t
            atomicAdd(&g_cnt[img16 * 3 + slot], v);
        }
    }
}

// ---------------------------------------------------------------------------
// Kernel 3: intersection popcounts (128 blocks, 8 per image)
// ---------------------------------------------------------------------------
__global__ __launch_bounds__(256) void k_inter() {
    const int b = blockIdx.x;          // 0..127
    const int img = b >> 3;
    const int chunk = b & 7;
    const int tid = threadIdx.x;
    const int base = img * WPI + chunk * 1024;

    int li = 0;
#pragma unroll
    for (int k = 0; k < 4; ++k) {
        int w = base + tid + k * 256;
        li += __popc(g_pbits[w] & g_tbits[w]);
    }
#pragma unroll
    for (int off = 16; off; off >>= 1)
        li += __shfl_down_sync(0xffffffffu, li, off);
    __shared__ int s[8];
    if ((tid & 31) == 0) s[tid >> 5] = li;
    __syncthreads();
    if (tid == 0) {
        int v = s[0] + s[1] + s[2] + s[3] + s[4] + s[5] + s[6] + s[7];
        atomicAdd(&g_cnt[img * 3 + 0], v);
    }
}

// ---------------------------------------------------------------------------
// Kernel 4: final scalar combine
// ---------------------------------------------------------------------------
__global__ void k_combine(float* __restrict__ out) {
    double scl = 0.0;
    for (int b = 0; b < NB; ++b) {
        double I = (double)g_cnt[b * 3 + 0];
        double P = (double)g_cnt[b * 3 + 1];
        double T = (double)g_cnt[b * 3 + 2];
        scl += (2.0 * I + SMOOTHV) / (P + T + SMOOTHV);
    }
    double I0 = g_acc[0], I1 = g_acc[1], S0v = g_acc[2];
    double S1v = g_acc[3], F = g_acc[4], C1 = g_acc[5];
    double C0 = (double)NPIX - C1;
    double dice = 1.0 - 0.5 * ((2.0 * I0 + SMOOTHV) / (S0v + C0 + SMOOTHV) +
                               (2.0 * I1 + SMOOTHV) / (S1v + C1 + SMOOTHV));
    double focal = F / (double)NPIX;
    double cl = 1.0 - scl / (double)NB;
    out[0] = (float)(0.7 * cl + 0.1 * dice + 0.2 * focal);
}

extern "C" void kernel_launch(void* const* d_in, const int* in_sizes, int n_in,
                              void* d_out, int out_size) {
    const float* logits = (const float*)d_in[0];   // [16,2,512,512] f32
    const int*   truth  = (const int*)d_in[1];     // [16,512,512] i32
    float* out = (float*)d_out;

    k_init<<<1, 64>>>();
    k_pixel<<<512, 1024>>>(logits, truth);
    k_skel<<<NB * 2 * CSIZE, 1024>>>();
    k_inter<<<128, 256>>>();
    k_combine<<<1, 1>>>(out);
}

// round 7
// speedup vs baseline: 1.9777x; 1.0174x over previous
#include <cuda_runtime.h>
#include <cooperative_groups.h>
#include <stdint.h>

namespace cg = cooperative_groups;

// Problem constants (fixed shapes for this problem instance)
#define NB    16
#define HWPIX (512 * 512)          // pixels per image
#define NPIX  (NB * HWPIX)         // total pixels
#define WPI   8192                 // 32-bit words per bitpacked image (512 rows * 16 words)
#define SMOOTHV 1e-6
#define CSIZE 4                    // CTAs per image (cluster size)
#define WPC   (WPI / CSIZE)        // 2048 words per CTA
#define RPC   128                  // rows per CTA

// Scratch: bitpacked binarized images / skeletons
__device__ uint32_t g_pbits[NB * WPI];
__device__ uint32_t g_tbits[NB * WPI];

// Reduction state, zeroed by one cudaMemsetAsync per launch.
// acc: [0]=inter_c0 [1]=inter_c1 [2]=sum_p0 [3]=sum_p1 [4]=focal [5]=cnt_true1
// cnt: per image {inter, sum_p, sum_t}
struct Red { double acc[6]; int cnt[NB * 3]; };
__device__ Red g_red;

// ---------------------------------------------------------------------------
// Kernel 1: softmax + focal + dice partials + bitpacked binarization
// ---------------------------------------------------------------------------
__global__ __launch_bounds__(1024) void k_pixel(const float* __restrict__ logits,
                                                const int* __restrict__ truth) {
    const int tid  = threadIdx.x;
    const int lane = tid & 31;
    const int warp = tid >> 5;
    const int base = blockIdx.x * 8192 + warp * 256;

    float aI0 = 0.f, aI1 = 0.f, aS0 = 0.f, aS1 = 0.f, aF = 0.f, aC1 = 0.f;

#pragma unroll
    for (int k = 0; k < 8; ++k) {
        int pix = base + k * 32 + lane;
        int b   = pix >> 18;            // / HWPIX
        int i   = pix & (HWPIX - 1);
        float l0 = logits[(size_t)b * 2 * HWPIX + i];
        float l1 = logits[(size_t)b * 2 * HWPIX + HWPIX + i];
        int   tv = truth[pix];

        float d  = l0 - l1;
        float ad = fabsf(d);
        float u  = __expf(-ad);
        float pmax = 1.0f / (1.0f + u);
        float pmin = 1.0f - pmax;
        bool  pb = (d < 0.0f);
        bool  tb = (tv > 0);
        float p1 = pb ? pmax : pmin;
        float p0 = 1.0f - p1;
        float lg = __logf(1.0f + u);
        float ce = (pb == tb) ? lg : (ad + lg);
        float pt = tb ? p1 : p0;
        float om = 1.0f - pt;
        aF += 0.25f * om * om * ce;
        if (tb) { aI1 += p1; aC1 += 1.0f; } else { aI0 += p0; }
        aS0 += p0; aS1 += p1;

        unsigned pm = __ballot_sync(0xffffffffu, pb);
        unsigned tm = __ballot_sync(0xffffffffu, tb);
        if (lane == 0) {
            int w = (base + k * 32) >> 5;
            g_pbits[w] = pm;
            g_tbits[w] = tm;
        }
    }

    __shared__ float red[32][6];
#pragma unroll
    for (int off = 16; off; off >>= 1) {
        aI0 += __shfl_down_sync(0xffffffffu, aI0, off);
        aI1 += __shfl_down_sync(0xffffffffu, aI1, off);
        aS0 += __shfl_down_sync(0xffffffffu, aS0, off);
        aS1 += __shfl_down_sync(0xffffffffu, aS1, off);
        aF  += __shfl_down_sync(0xffffffffu, aF , off);
        aC1 += __shfl_down_sync(0xffffffffu, aC1, off);
    }
    if (lane == 0) {
        red[warp][0] = aI0; red[warp][1] = aI1; red[warp][2] = aS0;
        red[warp][3] = aS1; red[warp][4] = aF;  red[warp][5] = aC1;
    }
    __syncthreads();
    if (warp == 0) {
        float v0 = red[lane][0], v1 = red[lane][1], v2 = red[lane][2];
        float v3 = red[lane][3], v4 = red[lane][4], v5 = red[lane][5];
#pragma unroll
        for (int off = 16; off; off >>= 1) {
            v0 += __shfl_down_sync(0xffffffffu, v0, off);
            v1 += __shfl_down_sync(0xffffffffu, v1, off);
            v2 += __shfl_down_sync(0xffffffffu, v2, off);
            v3 += __shfl_down_sync(0xffffffffu, v3, off);
            v4 += __shfl_down_sync(0xffffffffu, v4, off);
            v5 += __shfl_down_sync(0xffffffffu, v5, off);
        }
        if (lane == 0) {
            atomicAdd(&g_red.acc[0], (double)v0);
            atomicAdd(&g_red.acc[1], (double)v1);
            atomicAdd(&g_red.acc[2], (double)v2);
            atomicAdd(&g_red.acc[3], (double)v3);
            atomicAdd(&g_red.acc[4], (double)v4);
            atomicAdd(&g_red.acc[5], (double)v5);
        }
    }
}

// ---------------------------------------------------------------------------
// Kernel 2: Zhang-Suen skeletonization, 4-CTA cluster per image, bit-parallel,
// double-buffered, word-level change masks, parity-flag convergence
// (exactly 2 cluster.syncs per iteration).
// ---------------------------------------------------------------------------
__device__ __forceinline__ void fadd(uint32_t a, uint32_t b, uint32_t c,
                                     uint32_t& s, uint32_t& cy) {
    uint32_t x = a ^ b; s = x ^ c; cy = (a & b) | (x & c);
}
__device__ __forceinline__ void hadd(uint32_t a, uint32_t b,
                                     uint32_t& s, uint32_t& cy) {
    s = a ^ b; cy = a & b;
}

template <int SUB>
__device__ __forceinline__ uint32_t thin_word(const uint32_t* img, int idx, int c) {
    uint32_t cur = img[idx];
    if (!cur) return 0u;
    bool cL = c > 0, cR = c < 15;
    uint32_t up = img[idx - 16];
    uint32_t dn = img[idx + 16];
    uint32_t lf = cL ? img[idx - 1]  : 0u;
    uint32_t rt = cR ? img[idx + 1]  : 0u;
    uint32_t ul = cL ? img[idx - 17] : 0u;
    uint32_t ur = cR ? img[idx - 15] : 0u;
    uint32_t dl = cL ? img[idx + 15] : 0u;
    uint32_t dr = cR ? img[idx + 17] : 0u;

    uint32_t p2 = up;                                 // N
    uint32_t p3 = (up >> 1) | (ur << 31);             // NE
    uint32_t p4 = (cur >> 1) | (rt << 31);            // E
    uint32_t p5 = (dn >> 1) | (dr << 31);             // SE
    uint32_t p6 = dn;                                 // S
    uint32_t p7 = (dn << 1) | (dl >> 31);             // SW
    uint32_t p8 = (cur << 1) | (lf >> 31);            // W
    uint32_t p9 = (up << 1) | (ul >> 31);             // NW

    uint32_t s1, c1, s2, c2, s3, c3, S0, c4, s5, c5, S1, c6, S2, S3;
    fadd(p2, p3, p4, s1, c1);
    fadd(p5, p6, p7, s2, c2);
    hadd(p8, p9, s3, c3);
    fadd(s1, s2, s3, S0, c4);
    fadd(c1, c2, c3, s5, c5);
    hadd(s5, c4, S1, c6);
    hadd(c5, c6, S2, S3);
    uint32_t ge2 = S1 | S2 | S3;
    uint32_t le6 = ~(S3 | (S2 & S1 & S0));

    uint32_t t0 = ~p2 & p3, t1 = ~p3 & p4, t2 = ~p4 & p5, t3 = ~p5 & p6;
    uint32_t t4 = ~p6 & p7, t5 = ~p7 & p8, t6 = ~p8 & p9, t7 = ~p9 & p2;
    uint32_t a1, d1, a2, d2, a3, d3, A0, d4, a5, d5, A1, d6, A2, A3;
    fadd(t0, t1, t2, a1, d1);
    fadd(t3, t4, t5, a2, d2);
    hadd(t6, t7, a3, d3);
    fadd(a1, a2, a3, A0, d4);
    fadd(d1, d2, d3, a5, d5);
    hadd(a5, d4, A1, d6);
    hadd(d5, d6, A2, A3);
    uint32_t aeq1 = A0 & ~(A1 | A2 | A3);

    uint32_t cond34;
    if (SUB == 0)
        cond34 = ~(p4 & p6 & (p2 | p8));
    else
        cond34 = ~(p2 & p8 & (p4 | p6));

    uint32_t remove = cur & ge2 & le6 & aeq1 & cond34;
    return cur & ~remove;
}

#define BWORDS ((RPC + 2) * 16)   // 2080 words per buffer (halo rows 0 and 129)
#define CROWS  (RPC + 2)

__global__ __launch_bounds__(1024) __cluster_dims__(CSIZE, 1, 1)
void k_skel() {
    __shared__ uint32_t buf[2][BWORDS];   // ping-pong image buffers
    __shared__ uint32_t chg[3][CROWS];    // per-row 16-bit word-change masks, 3 rotating slots
    __shared__ uint32_t rc[CROWS];        // combined masks (last two sub-passes)
    __shared__ int s_flag[2];             // parity-indexed convergence flags
    __shared__ int s_rem[CSIZE];

    const int tid = threadIdx.x;
    cg::cluster_group cluster = cg::this_cluster();
    const unsigned rank = cluster.block_rank();
    const unsigned image = blockIdx.x / CSIZE;

    uint32_t* src = (image < NB) ? &g_pbits[image * WPI]
                                 : &g_tbits[(image - NB) * WPI];
    uint32_t* my = src + rank * WPC;

    const bool hasUp = (rank > 0), hasDn = (rank + 1 < CSIZE);
    uint32_t* pu_buf = hasUp ? (uint32_t*)cluster.map_shared_rank((void*)buf, rank - 1) : nullptr;
    uint32_t* pd_buf = hasDn ? (uint32_t*)cluster.map_shared_rank((void*)buf, rank + 1) : nullptr;
    volatile uint32_t* pu_chg = hasUp ? (volatile uint32_t*)cluster.map_shared_rank((void*)chg, rank - 1) : nullptr;
    volatile uint32_t* pd_chg = hasDn ? (volatile uint32_t*)cluster.map_shared_rank((void*)chg, rank + 1) : nullptr;

    // load own 128 rows into buf[0] rows 1..128
#pragma unroll
    for (int k = 0; k < 2; ++k) {
        int w = tid + k * 1024;
        buf[0][16 + w] = my[w];
    }
    if (tid < CROWS) { chg[1][tid] = 0xFFFFu; chg[2][tid] = 0xFFFFu; }
    if (tid < 2) s_flag[tid] = 0;
    cluster.sync();

    int p = 0;                   // current buffer parity (returns to 0 each iter)
    int tw = 0, t1 = 1, t2 = 2;  // chg slots: write / last pass / pass before

    for (int iter = 0; iter < 512; ++iter) {
        const int q = iter & 1;
        // Reset slot q. Peers last read it at the end of iteration iter-2;
        // two cluster.syncs (iteration iter-1) have passed since -> safe.
        if (tid == 0) s_flag[q] = 0;
        int changed = 0;

#pragma unroll
        for (int sub = 0; sub < 2; ++sub) {
            uint32_t* cur = buf[p];
            uint32_t* nxt = buf[p ^ 1];

            // halo copy + combined word-change masks (slots t1|t2)
            if (tid < 16) {
                cur[tid] = hasUp ? pu_buf[p * BWORDS + RPC * 16 + tid] : 0u;
            } else if (tid < 32) {
                cur[(RPC + 1) * 16 + (tid - 16)] =
                    hasDn ? pd_buf[p * BWORDS + 16 + (tid - 16)] : 0u;
            } else if (tid < 32 + CROWS) {
                int r = tid - 32;
                uint32_t v;
                if (r == 0)
                    v = hasUp ? (pu_chg[t1 * CROWS + RPC] |
                                 pu_chg[t2 * CROWS + RPC]) : 0u;
                else if (r == RPC + 1)
                    v = hasDn ? (pd_chg[t1 * CROWS + 1] |
                                 pd_chg[t2 * CROWS + 1]) : 0u;
                else
                    v = chg[t1][r] | chg[t2][r];
                rc[r] = v;
            }
            __syncthreads();

#pragma unroll
            for (int k = 0; k < 2; ++k) {
                int w = tid + k * 1024;
                int r = (w >> 4) + 1;
                int c = w & 15;
                int idx = 16 + w;
                uint32_t o = cur[idx];
                // word (r,c) active iff any of 9 neighbor words changed in
                // the last two sub-passes
                uint32_t nb = rc[r - 1] | rc[r] | rc[r + 1];
                nb |= (nb << 1) | (nb >> 1);
                uint32_t n = o;
                if ((nb >> c) & 1u)
                    n = (sub == 0) ? thin_word<0>(cur, idx, c)
                                   : thin_word<1>(cur, idx, c);
                nxt[idx] = n;
                unsigned bm = __ballot_sync(0xffffffffu, n != o);
                changed |= (bm != 0u);
                int ln = tid & 31;
                if (ln == 0)       chg[tw][r] = bm & 0xFFFFu;   // low half-warp row
                else if (ln == 16) chg[tw][r] = bm >> 16;       // high half-warp row
            }
            if (sub == 1 && changed) s_flag[q] = 1;
            cluster.sync();

            p ^= 1;
            int tmp = t2; t2 = t1; t1 = tw; tw = tmp;
        }

        // convergence: peers' flags for this iteration are visible after the
        // sub==1 cluster.sync above. No extra cluster.sync needed.
        if (tid < CSIZE)
            s_rem[tid] = *(volatile int*)cluster.map_shared_rank((void*)&s_flag[q], tid);
        __syncthreads();
        if (!(s_rem[0] | s_rem[1] | s_rem[2] | s_rem[3])) break;
    }

    // store result + per-CTA popcounts for clDice (sum_p / sum_t)
    int pcnt = 0;
#pragma unroll
    for (int k = 0; k < 2; ++k) {
        int w = tid + k * 1024;
        uint32_t v = buf[p][16 + w];
        my[w] = v;
        pcnt += __popc(v);
    }
#pragma unroll
    for (int off = 16; off; off >>= 1)
        pcnt += __shfl_down_sync(0xffffffffu, pcnt, off);
    __shared__ int sred[32];
    if ((tid & 31) == 0) sred[tid >> 5] = pcnt;
    __syncthreads();
    if (tid < 32) {
        int v = sred[tid];
#pragma unroll
        for (int off = 16; off; off >>= 1)
            v += __shfl_down_sync(0xffffffffu, v, off);
        if (tid == 0) {
            int img16 = (image < NB) ? (int)image : (int)(image - NB);
            int slot = (image < NB) ? 1 : 2;  // sum_p or sum_t
            atomicAdd(&g_red.cnt[img16 * 3 + slot], v);
        }
    }
}

// ---------------------------------------------------------------------------
// Kernel 3: intersection popcounts (128 blocks x 256 threads, uint4 loads)
// ---------------------------------------------------------------------------
__global__ __launch_bounds__(256) void k_inter() {
    const int idx = blockIdx.x * 256 + threadIdx.x;   // 0..32767 uint4 index
    const int img = blockIdx.x >> 3;                  // 8 blocks per image (2048 uint4)
    const uint4 a = reinterpret_cast<const uint4*>(g_pbits)[idx];
    const uint4 b = reinterpret_cast<const uint4*>(g_tbits)[idx];
    int li = __popc(a.x & b.x) + __popc(a.y & b.y) +
             __popc(a.z & b.z) + __popc(a.w & b.w);
#pragma unroll
    for (int off = 16; off; off >>= 1)
        li += __shfl_down_sync(0xffffffffu, li, off);
    __shared__ int s[8];
    if ((threadIdx.x & 31) == 0) s[threadIdx.x >> 5] = li;
    __syncthreads();
    if (threadIdx.x == 0) {
        int v = s[0] + s[1] + s[2] + s[3] + s[4] + s[5] + s[6] + s[7];
        atomicAdd(&g_red.cnt[img * 3 + 0], v);
    }
}

// ---------------------------------------------------------------------------
// Kernel 4: final scalar combine
// ---------------------------------------------------------------------------
__global__ void k_combine(float* __restrict__ out) {
    double scl = 0.0;
    for (int b = 0; b < NB; ++b) {
        double I = (double)g_red.cnt[b * 3 + 0];
        double P = (double)g_red.cnt[b * 3 + 1];
        double T = (double)g_red.cnt[b * 3 + 2];
        scl += (2.0 * I + SMOOTHV) / (P + T + SMOOTHV);
    }
    double I0 = g_red.acc[0], I1 = g_red.acc[1], S0v = g_red.acc[2];
    double S1v = g_red.acc[3], F = g_red.acc[4], C1 = g_red.acc[5];
    double C0 = (double)NPIX - C1;
    double dice = 1.0 - 0.5 * ((2.0 * I0 + SMOOTHV) / (S0v + C0 + SMOOTHV) +
                               (2.0 * I1 + SMOOTHV) / (S1v + C1 + SMOOTHV));
    double focal = F / (double)NPIX;
    double cl = 1.0 - scl / (double)NB;
    out[0] = (float)(0.7 * cl + 0.1 * dice + 0.2 * focal);
}

extern "C" void kernel_launch(void* const* d_in, const int* in_sizes, int n_in,
                              void* d_out, int out_size) {
    const float* logits = (const float*)d_in[0];   // [16,2,512,512] f32
    const int*   truth  = (const int*)d_in[1];     // [16,512,512] i32
    float* out = (float*)d_out;

    void* redp = nullptr;
    cudaGetSymbolAddress(&redp, g_red);
    cudaMemsetAsync(redp, 0, sizeof(Red), 0);

    k_pixel<<<512, 1024>>>(logits, truth);
    k_skel<<<NB * 2 * CSIZE, 1024>>>();
    k_inter<<<128, 256>>>();
    k_combine<<<1, 1>>>(out);
}

// round 8
// speedup vs baseline: 2.3312x; 1.1787x over previous
#include <cuda_runtime.h>
#include <cooperative_groups.h>
#include <stdint.h>

namespace cg = cooperative_groups;

// Problem constants (fixed shapes for this problem instance)
#define NB    16
#define HWPIX (512 * 512)          // pixels per image
#define NPIX  (NB * HWPIX)         // total pixels
#define WPI   8192                 // 32-bit words per bitpacked image (512 rows * 16 words)
#define SMOOTHV 1e-6
#define CSIZE 4                    // CTAs per image (cluster size)
#define WPC   (WPI / CSIZE)        // 2048 words per CTA
#define RPC   128                  // rows per CTA

// Scratch: bitpacked binarized images / skeletons
__device__ uint32_t g_pbits[NB * WPI];
__device__ uint32_t g_tbits[NB * WPI];

// Reduction state, zeroed by one cudaMemsetAsync per launch.
// acc: [0]=inter_c0 [1]=inter_c1 [2]=sum_p0 [3]=sum_p1 [4]=focal [5]=cnt_true1
// cnt: per image {inter, sum_p, sum_t}; ticket: last-block election for combine
struct Red { double acc[6]; int cnt[NB * 3]; unsigned int ticket; };
__device__ Red g_red;

// ---------------------------------------------------------------------------
// Kernel 1: softmax + focal + dice partials + bitpacked binarization
// ---------------------------------------------------------------------------
__global__ __launch_bounds__(1024) void k_pixel(const float* __restrict__ logits,
                                                const int* __restrict__ truth) {
    const int tid  = threadIdx.x;
    const int lane = tid & 31;
    const int warp = tid >> 5;
    const int base = blockIdx.x * 8192 + warp * 256;

    float aI0 = 0.f, aI1 = 0.f, aS0 = 0.f, aS1 = 0.f, aF = 0.f, aC1 = 0.f;

#pragma unroll
    for (int k = 0; k < 8; ++k) {
        int pix = base + k * 32 + lane;
        int b   = pix >> 18;            // / HWPIX
        int i   = pix & (HWPIX - 1);
        float l0 = logits[(size_t)b * 2 * HWPIX + i];
        float l1 = logits[(size_t)b * 2 * HWPIX + HWPIX + i];
        int   tv = truth[pix];

        float d  = l0 - l1;
        float ad = fabsf(d);
        float u  = __expf(-ad);
        float pmax = 1.0f / (1.0f + u);
        float pmin = 1.0f - pmax;
        bool  pb = (d < 0.0f);
        bool  tb = (tv > 0);
        float p1 = pb ? pmax : pmin;
        float p0 = 1.0f - p1;
        float lg = __logf(1.0f + u);
        float ce = (pb == tb) ? lg : (ad + lg);
        float pt = tb ? p1 : p0;
        float om = 1.0f - pt;
        aF += 0.25f * om * om * ce;
        if (tb) { aI1 += p1; aC1 += 1.0f; } else { aI0 += p0; }
        aS0 += p0; aS1 += p1;

        unsigned pm = __ballot_sync(0xffffffffu, pb);
        unsigned tm = __ballot_sync(0xffffffffu, tb);
        if (lane == 0) {
            int w = (base + k * 32) >> 5;
            g_pbits[w] = pm;
            g_tbits[w] = tm;
        }
    }

    __shared__ float red[32][6];
#pragma unroll
    for (int off = 16; off; off >>= 1) {
        aI0 += __shfl_down_sync(0xffffffffu, aI0, off);
        aI1 += __shfl_down_sync(0xffffffffu, aI1, off);
        aS0 += __shfl_down_sync(0xffffffffu, aS0, off);
        aS1 += __shfl_down_sync(0xffffffffu, aS1, off);
        aF  += __shfl_down_sync(0xffffffffu, aF , off);
        aC1 += __shfl_down_sync(0xffffffffu, aC1, off);
    }
    if (lane == 0) {
        red[warp][0] = aI0; red[warp][1] = aI1; red[warp][2] = aS0;
        red[warp][3] = aS1; red[warp][4] = aF;  red[warp][5] = aC1;
    }
    __syncthreads();
    if (warp == 0) {
        float v0 = red[lane][0], v1 = red[lane][1], v2 = red[lane][2];
        float v3 = red[lane][3], v4 = red[lane][4], v5 = red[lane][5];
#pragma unroll
        for (int off = 16; off; off >>= 1) {
            v0 += __shfl_down_sync(0xffffffffu, v0, off);
            v1 += __shfl_down_sync(0xffffffffu, v1, off);
            v2 += __shfl_down_sync(0xffffffffu, v2, off);
            v3 += __shfl_down_sync(0xffffffffu, v3, off);
            v4 += __shfl_down_sync(0xffffffffu, v4, off);
            v5 += __shfl_down_sync(0xffffffffu, v5, off);
        }
        if (lane == 0) {
            atomicAdd(&g_red.acc[0], (double)v0);
            atomicAdd(&g_red.acc[1], (double)v1);
            atomicAdd(&g_red.acc[2], (double)v2);
            atomicAdd(&g_red.acc[3], (double)v3);
            atomicAdd(&g_red.acc[4], (double)v4);
            atomicAdd(&g_red.acc[5], (double)v5);
        }
    }
}

// ---------------------------------------------------------------------------
// Kernel 2: Zhang-Suen skeletonization, 4-CTA cluster per image, bit-parallel,
// double-buffered, word-level change masks, parity-flag convergence
// (exactly 2 cluster.syncs per iteration).
// ---------------------------------------------------------------------------
__device__ __forceinline__ void fadd(uint32_t a, uint32_t b, uint32_t c,
                                     uint32_t& s, uint32_t& cy) {
    uint32_t x = a ^ b; s = x ^ c; cy = (a & b) | (x & c);
}
__device__ __forceinline__ void hadd(uint32_t a, uint32_t b,
                                     uint32_t& s, uint32_t& cy) {
    s = a ^ b; cy = a & b;
}

template <int SUB>
__device__ __forceinline__ uint32_t thin_word(const uint32_t* img, int idx, int c) {
    uint32_t cur = img[idx];
    if (!cur) return 0u;
    bool cL = c > 0, cR = c < 15;
    uint32_t up = img[idx - 16];
    uint32_t dn = img[idx + 16];
    uint32_t lf = cL ? img[idx - 1]  : 0u;
    uint32_t rt = cR ? img[idx + 1]  : 0u;
    uint32_t ul = cL ? img[idx - 17] : 0u;
    uint32_t ur = cR ? img[idx - 15] : 0u;
    uint32_t dl = cL ? img[idx + 15] : 0u;
    uint32_t dr = cR ? img[idx + 17] : 0u;

    uint32_t p2 = up;                                 // N
    uint32_t p3 = (up >> 1) | (ur << 31);             // NE
    uint32_t p4 = (cur >> 1) | (rt << 31);            // E
    uint32_t p5 = (dn >> 1) | (dr << 31);             // SE
    uint32_t p6 = dn;                                 // S
    uint32_t p7 = (dn << 1) | (dl >> 31);             // SW
    uint32_t p8 = (cur << 1) | (lf >> 31);            // W
    uint32_t p9 = (up << 1) | (ul >> 31);             // NW

    uint32_t s1, c1, s2, c2, s3, c3, S0, c4, s5, c5, S1, c6, S2, S3;
    fadd(p2, p3, p4, s1, c1);
    fadd(p5, p6, p7, s2, c2);
    hadd(p8, p9, s3, c3);
    fadd(s1, s2, s3, S0, c4);
    fadd(c1, c2, c3, s5, c5);
    hadd(s5, c4, S1, c6);
    hadd(c5, c6, S2, S3);
    uint32_t ge2 = S1 | S2 | S3;
    uint32_t le6 = ~(S3 | (S2 & S1 & S0));

    uint32_t t0 = ~p2 & p3, t1 = ~p3 & p4, t2 = ~p4 & p5, t3 = ~p5 & p6;
    uint32_t t4 = ~p6 & p7, t5 = ~p7 & p8, t6 = ~p8 & p9, t7 = ~p9 & p2;
    uint32_t a1, d1, a2, d2, a3, d3, A0, d4, a5, d5, A1, d6, A2, A3;
    fadd(t0, t1, t2, a1, d1);
    fadd(t3, t4, t5, a2, d2);
    hadd(t6, t7, a3, d3);
    fadd(a1, a2, a3, A0, d4);
    fadd(d1, d2, d3, a5, d5);
    hadd(a5, d4, A1, d6);
    hadd(d5, d6, A2, A3);
    uint32_t aeq1 = A0 & ~(A1 | A2 | A3);

    uint32_t cond34;
    if (SUB == 0)
        cond34 = ~(p4 & p6 & (p2 | p8));
    else
        cond34 = ~(p2 & p8 & (p4 | p6));

    uint32_t remove = cur & ge2 & le6 & aeq1 & cond34;
    return cur & ~remove;
}

#define BWORDS ((RPC + 2) * 16)   // 2080 words per buffer (halo rows 0 and 129)
#define CROWS  (RPC + 2)

__global__ __launch_bounds__(1024) __cluster_dims__(CSIZE, 1, 1)
void k_skel() {
    __shared__ uint32_t buf[2][BWORDS];   // ping-pong image buffers
    __shared__ uint32_t chg[3][CROWS];    // per-row 16-bit word-change masks, 3 rotating slots
    __shared__ uint32_t rc[CROWS];        // combined masks (last two sub-passes)
    __shared__ int s_flag[2];             // parity-indexed convergence flags
    __shared__ int s_rem[CSIZE];

    const int tid = threadIdx.x;
    cg::cluster_group cluster = cg::this_cluster();
    const unsigned rank = cluster.block_rank();
    const unsigned image = blockIdx.x / CSIZE;

    uint32_t* src = (image < NB) ? &g_pbits[image * WPI]
                                 : &g_tbits[(image - NB) * WPI];
    uint32_t* my = src + rank * WPC;

    const bool hasUp = (rank > 0), hasDn = (rank + 1 < CSIZE);
    uint32_t* pu_buf = hasUp ? (uint32_t*)cluster.map_shared_rank((void*)buf, rank - 1) : nullptr;
    uint32_t* pd_buf = hasDn ? (uint32_t*)cluster.map_shared_rank((void*)buf, rank + 1) : nullptr;
    volatile uint32_t* pu_chg = hasUp ? (volatile uint32_t*)cluster.map_shared_rank((void*)chg, rank - 1) : nullptr;
    volatile uint32_t* pd_chg = hasDn ? (volatile uint32_t*)cluster.map_shared_rank((void*)chg, rank + 1) : nullptr;

    // load own 128 rows into buf[0] rows 1..128
#pragma unroll
    for (int k = 0; k < 2; ++k) {
        int w = tid + k * 1024;
        buf[0][16 + w] = my[w];
    }
    if (tid < CROWS) { chg[1][tid] = 0xFFFFu; chg[2][tid] = 0xFFFFu; }
    if (tid < 2) s_flag[tid] = 0;
    cluster.sync();

    int p = 0;                   // current buffer parity (returns to 0 each iter)
    int tw = 0, t1 = 1, t2 = 2;  // chg slots: write / last pass / pass before

    for (int iter = 0; iter < 512; ++iter) {
        const int q = iter & 1;
        // Reset slot q. Peers last read it at the end of iteration iter-2;
        // two cluster.syncs (iteration iter-1) have passed since -> safe.
        if (tid == 0) s_flag[q] = 0;
        int changed = 0;

#pragma unroll
        for (int sub = 0; sub < 2; ++sub) {
            uint32_t* cur = buf[p];
            uint32_t* nxt = buf[p ^ 1];

            // halo copy + combined word-change masks (slots t1|t2)
            if (tid < 16) {
                cur[tid] = hasUp ? pu_buf[p * BWORDS + RPC * 16 + tid] : 0u;
            } else if (tid < 32) {
                cur[(RPC + 1) * 16 + (tid - 16)] =
                    hasDn ? pd_buf[p * BWORDS + 16 + (tid - 16)] : 0u;
            } else if (tid < 32 + CROWS) {
                int r = tid - 32;
                uint32_t v;
                if (r == 0)
                    v = hasUp ? (pu_chg[t1 * CROWS + RPC] |
                                 pu_chg[t2 * CROWS + RPC]) : 0u;
                else if (r == RPC + 1)
                    v = hasDn ? (pd_chg[t1 * CROWS + 1] |
                                 pd_chg[t2 * CROWS + 1]) : 0u;
                else
                    v = chg[t1][r] | chg[t2][r];
                rc[r] = v;
            }
            __syncthreads();

#pragma unroll
            for (int k = 0; k < 2; ++k) {
                int w = tid + k * 1024;
                int r = (w >> 4) + 1;
                int c = w & 15;
                int idx = 16 + w;
                uint32_t o = cur[idx];
                // word (r,c) active iff any of 9 neighbor words changed in
                // the last two sub-passes
                uint32_t nb = rc[r - 1] | rc[r] | rc[r + 1];
                nb |= (nb << 1) | (nb >> 1);
                uint32_t n = o;
                if ((nb >> c) & 1u)
                    n = (sub == 0) ? thin_word<0>(cur, idx, c)
                                   : thin_word<1>(cur, idx, c);
                nxt[idx] = n;
                unsigned bm = __ballot_sync(0xffffffffu, n != o);
                changed |= (bm != 0u);
                int ln = tid & 31;
                if (ln == 0)       chg[tw][r] = bm & 0xFFFFu;   // low half-warp row
                else if (ln == 16) chg[tw][r] = bm >> 16;       // high half-warp row
            }
            if (sub == 1 && changed) s_flag[q] = 1;
            cluster.sync();

            p ^= 1;
            int tmp = t2; t2 = t1; t1 = tw; tw = tmp;
        }

        // convergence: peers' flags for this iteration are visible after the
        // sub==1 cluster.sync above. No extra cluster.sync needed.
        if (tid < CSIZE)
            s_rem[tid] = *(volatile int*)cluster.map_shared_rank((void*)&s_flag[q], tid);
        __syncthreads();
        if (!(s_rem[0] | s_rem[1] | s_rem[2] | s_rem[3])) break;
    }

    // store result + per-CTA popcounts for clDice (sum_p / sum_t)
    int pcnt = 0;
#pragma unroll
    for (int k = 0; k < 2; ++k) {
        int w = tid + k * 1024;
        uint32_t v = buf[p][16 + w];
        my[w] = v;
        pcnt += __popc(v);
    }
#pragma unroll
    for (int off = 16; off; off >>= 1)
        pcnt += __shfl_down_sync(0xffffffffu, pcnt, off);
    __shared__ int sred[32];
    if ((tid & 31) == 0) sred[tid >> 5] = pcnt;
    __syncthreads();
    if (tid < 32) {
        int v = sred[tid];
#pragma unroll
        for (int off = 16; off; off >>= 1)
            v += __shfl_down_sync(0xffffffffu, v, off);
        if (tid == 0) {
            int img16 = (image < NB) ? (int)image : (int)(image - NB);
            int slot = (image < NB) ? 1 : 2;  // sum_p or sum_t
            atomicAdd(&g_red.cnt[img16 * 3 + slot], v);
        }
    }
}

// ---------------------------------------------------------------------------
// Kernel 3: intersection popcounts (128 blocks x 256 threads, uint4 loads)
// + final scalar combine performed by the LAST block (ticket election).
// ---------------------------------------------------------------------------
__global__ __launch_bounds__(256) void k_inter(float* __restrict__ out) {
    const int idx = blockIdx.x * 256 + threadIdx.x;   // 0..32767 uint4 index
    const int img = blockIdx.x >> 3;                  // 8 blocks per image (2048 uint4)
    const int tid = threadIdx.x;
    const uint4 a = reinterpret_cast<const uint4*>(g_pbits)[idx];
    const uint4 b = reinterpret_cast<const uint4*>(g_tbits)[idx];
    int li = __popc(a.x & b.x) + __popc(a.y & b.y) +
             __popc(a.z & b.z) + __popc(a.w & b.w);
#pragma unroll
    for (int off = 16; off; off >>= 1)
        li += __shfl_down_sync(0xffffffffu, li, off);
    __shared__ int s[8];
    __shared__ int s_last;
    if ((tid & 31) == 0) s[tid >> 5] = li;
    __syncthreads();
    if (tid == 0) {
        int v = s[0] + s[1] + s[2] + s[3] + s[4] + s[5] + s[6] + s[7];
        atomicAdd(&g_red.cnt[img * 3 + 0], v);
        __threadfence();                                // cnt visible before ticket
        unsigned t = atomicAdd(&g_red.ticket, 1u);
        s_last = (t == 127u);                           // last block to finish
    }
    __syncthreads();
    if (!s_last || tid >= 32) return;

    // --- final combine, executed once by the last block's first warp ---
    // lanes 0..15: one clDice ratio each (parallel fp64 divides)
    double ratio = 0.0;
    if (tid < NB) {
        volatile int* c = g_red.cnt;
        double I = (double)c[tid * 3 + 0];
        double P = (double)c[tid * 3 + 1];
        double T = (double)c[tid * 3 + 2];
        ratio = (2.0 * I + SMOOTHV) / (P + T + SMOOTHV);
    }
#pragma unroll
    for (int off = 16; off; off >>= 1)
        ratio += __shfl_down_sync(0xffffffffu, ratio, off);
    if (tid == 0) {
        double I0 = g_red.acc[0], I1 = g_red.acc[1], S0v = g_red.acc[2];
        double S1v = g_red.acc[3], F = g_red.acc[4], C1 = g_red.acc[5];
        double C0 = (double)NPIX - C1;
        double dice = 1.0 - 0.5 * ((2.0 * I0 + SMOOTHV) / (S0v + C0 + SMOOTHV) +
                                   (2.0 * I1 + SMOOTHV) / (S1v + C1 + SMOOTHV));
        double focal = F / (double)NPIX;
        double cl = 1.0 - ratio / (double)NB;
        out[0] = (float)(0.7 * cl + 0.1 * dice + 0.2 * focal);
    }
}

extern "C" void kernel_launch(void* const* d_in, const int* in_sizes, int n_in,
                              void* d_out, int out_size) {
    const float* logits = (const float*)d_in[0];   // [16,2,512,512] f32
    const int*   truth  = (const int*)d_in[1];     // [16,512,512] i32
    float* out = (float*)d_out;

    void* redp = nullptr;
    cudaGetSymbolAddress(&redp, g_red);
    cudaMemsetAsync(redp, 0, sizeof(Red), 0);

    k_pixel<<<512, 1024>>>(logits, truth);
    k_skel<<<NB * 2 * CSIZE, 1024>>>();
    k_inter<<<128, 256>>>(out);
}